// round 1
// baseline (speedup 1.0000x reference)
#include <cuda_runtime.h>
#include <math.h>

// Problem dims (fixed by reference)
#define Bv 32
#define Sv 1024
#define Dv 1024
#define Av 256
#define Ev 16
#define Mrows (Bv * Sv)   // 32768

// Scratch (no cudaMalloc allowed) — __device__ globals
__device__ float g_h1[(size_t)Mrows * Av];   // after down-proj + GELU
__device__ float g_h2[(size_t)Mrows * Av];   // after expert + emb
__device__ float g_pre[(size_t)Mrows * Dv];  // pre-LN (up-proj + residual)
__device__ int   g_idx[Bv];
__device__ int   g_valid[Bv];

// ---------------------------------------------------------------------------
// domain_id may arrive as int32 or int64 depending on JAX x64 config.
// Detect: if stored as int64 (LE), the high words (odd int32 slots) of the
// first 16 values are all 0 or -1; genuine int32 ids (uniform 0..15) have
// ~(1/16)^16 chance of that. Normalize into g_idx / g_valid.
// ---------------------------------------------------------------------------
__global__ void prep_ids(const int* __restrict__ p) {
    bool is64 = true;
    for (int k = 0; k < 16; k++) {
        int hi = p[2 * k + 1];
        if (hi != 0 && hi != -1) { is64 = false; break; }
    }
    for (int b = 0; b < Bv; b++) {
        long long v;
        if (is64) {
            unsigned int lo = (unsigned int)p[2 * b];
            int hi = p[2 * b + 1];
            v = ((long long)hi << 32) | (long long)lo;
        } else {
            v = p[b];
        }
        g_valid[b] = (v >= 0 && v < Ev) ? 1 : 0;
        long long c = v < 0 ? 0 : (v > (Ev - 1) ? (Ev - 1) : v);
        g_idx[b] = (int)c;
    }
}

// ---------------------------------------------------------------------------
// Generic NT GEMM: C[M,N] = A[M,K] * B[N,K]^T with mode-specific epilogue.
// Tiles: 128x128x16, 256 threads, 8x8 per-thread micro-tile.
// MODE 1: C = GELU(A*B^T + bias)            -> g_h1   (A = hidden, B = down_W)
// MODE 2: per-batch expert: C = A*Wsel^T + bsel (or passthrough) + emb -> g_h2
// MODE 3: C = A*B^T + bias + residual        -> g_pre  (B = up_W)
// ---------------------------------------------------------------------------
template <int MODE>
__global__ __launch_bounds__(256, 2)
void gemm_nt(const float* __restrict__ Aext,
             const float* __restrict__ Bw,
             const float* __restrict__ bias,
             const float* __restrict__ extra) {
    constexpr int BM = 128, BN = 128, BK = 16;
    constexpr int N = (MODE == 3) ? Dv : Av;
    constexpr int K = (MODE == 1) ? Dv : Av;

    __shared__ float As[BK][BM + 4];
    __shared__ float Bs[BK][BN + 4];

    const int tid = threadIdx.x;
    const int tx = tid & 15;   // N direction (8 cols each)
    const int ty = tid >> 4;   // M direction (8 rows each)

    int m0;
    const int n0 = blockIdx.x * BN;
    const float* Ap;
    const float* Bp = Bw;
    const float* biasp = bias;
    const float* embp = nullptr;
    float* Cp;
    int valid = 1;

    if (MODE == 1) {
        m0 = blockIdx.y * BM;
        Ap = Aext;
        Cp = g_h1;
    } else if (MODE == 2) {
        const int b = blockIdx.z;
        const int e = g_idx[b];
        valid = g_valid[b];
        m0 = b * Sv + blockIdx.y * BM;
        Ap = g_h1;
        Bp = Bw + (size_t)e * Av * Av;
        biasp = bias + (size_t)e * Av;
        embp = extra + (size_t)e * Av;
        Cp = g_h2;
    } else {
        m0 = blockIdx.y * BM;
        Ap = g_h2;
        Cp = g_pre;
    }

    float acc[8][8];
#pragma unroll
    for (int i = 0; i < 8; i++)
#pragma unroll
        for (int j = 0; j < 8; j++) acc[i][j] = 0.f;

    for (int k0 = 0; k0 < K; k0 += BK) {
        // Load 128x16 tiles of A and B (float4, transpose into smem)
#pragma unroll
        for (int it = 0; it < 2; it++) {
            const int idx = tid + it * 256;
            const int r = idx >> 2;
            const int c4 = (idx & 3) * 4;
            float4 va = *(const float4*)(Ap + (size_t)(m0 + r) * K + k0 + c4);
            As[c4 + 0][r] = va.x;
            As[c4 + 1][r] = va.y;
            As[c4 + 2][r] = va.z;
            As[c4 + 3][r] = va.w;
            float4 vb = *(const float4*)(Bp + (size_t)(n0 + r) * K + k0 + c4);
            Bs[c4 + 0][r] = vb.x;
            Bs[c4 + 1][r] = vb.y;
            Bs[c4 + 2][r] = vb.z;
            Bs[c4 + 3][r] = vb.w;
        }
        __syncthreads();

#pragma unroll
        for (int kk = 0; kk < BK; kk++) {
            float a[8], bb[8];
#pragma unroll
            for (int i = 0; i < 8; i++) a[i] = As[kk][ty * 8 + i];
#pragma unroll
            for (int j = 0; j < 8; j++) bb[j] = Bs[kk][tx * 8 + j];
#pragma unroll
            for (int i = 0; i < 8; i++)
#pragma unroll
                for (int j = 0; j < 8; j++) acc[i][j] = fmaf(a[i], bb[j], acc[i][j]);
        }
        __syncthreads();
    }

    // Epilogue
#pragma unroll
    for (int i = 0; i < 8; i++) {
        const int r = m0 + ty * 8 + i;
#pragma unroll
        for (int j = 0; j < 8; j++) {
            const int c = n0 + tx * 8 + j;
            float v = acc[i][j];
            if (MODE == 1) {
                v += bias[c];
                v = 0.5f * v * (1.0f + erff(v * 0.70710678118654752440f));
                Cp[(size_t)r * Av + c] = v;
            } else if (MODE == 2) {
                float o;
                if (valid) o = v + biasp[c];
                else       o = g_h1[(size_t)r * Av + c];
                o += embp[c];
                Cp[(size_t)r * Av + c] = o;
            } else {
                v += bias[c] + extra[(size_t)r * Dv + c];
                Cp[(size_t)r * Dv + c] = v;
            }
        }
    }
}

// ---------------------------------------------------------------------------
// LayerNorm over D=1024. One block (256 threads) per row; each thread holds 4
// values in registers; two-pass (mean, then centered variance).
// ---------------------------------------------------------------------------
__global__ __launch_bounds__(256)
void ln_kernel(const float* __restrict__ gamma,
               const float* __restrict__ beta,
               float* __restrict__ out) {
    const int row = blockIdx.x;
    const int t = threadIdx.x;
    const float4 v = *(const float4*)(g_pre + (size_t)row * Dv + t * 4);

    __shared__ float red1[8];
    __shared__ float red2[8];

    float s = v.x + v.y + v.z + v.w;
#pragma unroll
    for (int o = 16; o; o >>= 1) s += __shfl_xor_sync(0xFFFFFFFFu, s, o);
    if ((t & 31) == 0) red1[t >> 5] = s;
    __syncthreads();
    float tot = 0.f;
#pragma unroll
    for (int i = 0; i < 8; i++) tot += red1[i];
    const float mu = tot * (1.0f / Dv);

    const float dx = v.x - mu, dy = v.y - mu, dz = v.z - mu, dw = v.w - mu;
    float s2 = dx * dx + dy * dy + dz * dz + dw * dw;
#pragma unroll
    for (int o = 16; o; o >>= 1) s2 += __shfl_xor_sync(0xFFFFFFFFu, s2, o);
    if ((t & 31) == 0) red2[t >> 5] = s2;
    __syncthreads();
    float tot2 = 0.f;
#pragma unroll
    for (int i = 0; i < 8; i++) tot2 += red2[i];
    const float inv = rsqrtf(tot2 * (1.0f / Dv) + 1e-5f);

    const int c = t * 4;
    const float4 gm = *(const float4*)(gamma + c);
    const float4 bt = *(const float4*)(beta + c);
    float4 o;
    o.x = dx * inv * gm.x + bt.x;
    o.y = dy * inv * gm.y + bt.y;
    o.z = dz * inv * gm.z + bt.z;
    o.w = dw * inv * gm.w + bt.w;
    *(float4*)(out + (size_t)row * Dv + c) = o;
}

// ---------------------------------------------------------------------------
extern "C" void kernel_launch(void* const* d_in, const int* in_sizes, int n_in,
                              void* d_out, int out_size) {
    const float* hidden     = (const float*)d_in[0];
    const int*   dom        = (const int*)d_in[1];
    const float* down_W     = (const float*)d_in[2];
    const float* down_b     = (const float*)d_in[3];
    const float* up_W       = (const float*)d_in[4];
    const float* up_b       = (const float*)d_in[5];
    const float* expert_W   = (const float*)d_in[6];
    const float* expert_b   = (const float*)d_in[7];
    const float* domain_emb = (const float*)d_in[8];
    const float* gamma      = (const float*)d_in[9];
    const float* beta       = (const float*)d_in[10];
    float* out = (float*)d_out;

    prep_ids<<<1, 1>>>(dom);

    // Stage 1: down-proj + GELU  (M=32768, N=256, K=1024)
    gemm_nt<1><<<dim3(Av / 128, Mrows / 128), 256>>>(hidden, down_W, down_b, nullptr);

    // Stage 2: per-batch expert + domain emb  (per batch: M=1024, N=256, K=256)
    gemm_nt<2><<<dim3(Av / 128, Sv / 128, Bv), 256>>>(nullptr, expert_W, expert_b, domain_emb);

    // Stage 3: up-proj + bias + residual  (M=32768, N=1024, K=256)
    gemm_nt<3><<<dim3(Dv / 128, Mrows / 128), 256>>>(nullptr, up_W, up_b, hidden);

    // Stage 4: LayerNorm
    ln_kernel<<<Mrows, 256>>>(gamma, beta, out);
}

// round 3
// speedup vs baseline: 2.4025x; 2.4025x over previous
#include <cuda_runtime.h>
#include <cuda_bf16.h>
#include <math.h>
#include <stdint.h>

// Problem dims (fixed)
#define Bv 32
#define Sv 1024
#define Dv 1024
#define Av 256
#define Ev 16
#define Mrows (Bv * Sv)   // 32768

// Scratch (no cudaMalloc allowed)
__device__ float g_h1[(size_t)Mrows * Av];   // after down-proj + GELU
__device__ float g_h2[(size_t)Mrows * Av];   // after expert + emb
__device__ float g_pre[(size_t)Mrows * Dv];  // pre-LN
__device__ int   g_idx[Bv];
__device__ int   g_valid[Bv];

// ---------------------------------------------------------------------------
__device__ __forceinline__ uint32_t smem_u32(const void* p) {
    uint32_t a;
    asm("{ .reg .u64 t; cvta.to.shared.u64 t, %1; cvt.u32.u64 %0, t; }" : "=r"(a) : "l"(p));
    return a;
}

#define LDSM4(r, addr) \
    asm volatile("ldmatrix.sync.aligned.m8n8.x4.shared.b16 {%0,%1,%2,%3}, [%4];" \
        : "=r"((r)[0]), "=r"((r)[1]), "=r"((r)[2]), "=r"((r)[3]) : "r"(addr))

#define MMA_OP(d, a, b0, b1) \
    asm volatile("mma.sync.aligned.m16n8k16.row.col.f32.bf16.bf16.f32 " \
        "{%0,%1,%2,%3}, {%4,%5,%6,%7}, {%8,%9}, {%0,%1,%2,%3};" \
        : "+f"((d)[0]), "+f"((d)[1]), "+f"((d)[2]), "+f"((d)[3]) \
        : "r"((a)[0]), "r"((a)[1]), "r"((a)[2]), "r"((a)[3]), "r"(b0), "r"(b1))

// ---------------------------------------------------------------------------
// domain_id may arrive as int32 or int64. Detect and normalize.
// ---------------------------------------------------------------------------
__global__ void prep_ids(const int* __restrict__ p) {
    bool is64 = true;
    for (int k = 0; k < 16; k++) {
        int hi = p[2 * k + 1];
        if (hi != 0 && hi != -1) { is64 = false; break; }
    }
    for (int b = 0; b < Bv; b++) {
        long long v;
        if (is64) {
            unsigned int lo = (unsigned int)p[2 * b];
            int hi = p[2 * b + 1];
            v = ((long long)hi << 32) | (long long)lo;
        } else {
            v = p[b];
        }
        g_valid[b] = (v >= 0 && v < Ev) ? 1 : 0;
        long long c = v < 0 ? 0 : (v > (Ev - 1) ? (Ev - 1) : v);
        g_idx[b] = (int)c;
    }
}

__device__ __forceinline__ float gelu_exact(float v) {
    return 0.5f * v * (1.0f + erff(v * 0.70710678118654752440f));
}

// Split fp32 float4 into hi/lo bf16 pairs and store 8B each (swizzle-safe).
__device__ __forceinline__ void split_store(char* hi_base, char* lo_base,
                                            uint32_t off, float4 v) {
    __nv_bfloat162 h0 = __floats2bfloat162_rn(v.x, v.y);
    __nv_bfloat162 h1 = __floats2bfloat162_rn(v.z, v.w);
    float2 f0 = __bfloat1622float2(h0);
    float2 f1 = __bfloat1622float2(h1);
    __nv_bfloat162 l0 = __floats2bfloat162_rn(v.x - f0.x, v.y - f0.y);
    __nv_bfloat162 l1 = __floats2bfloat162_rn(v.z - f1.x, v.w - f1.y);
    *(uint2*)(hi_base + off) = make_uint2(*(uint32_t*)&h0, *(uint32_t*)&h1);
    *(uint2*)(lo_base + off) = make_uint2(*(uint32_t*)&l0, *(uint32_t*)&l1);
}

// ---------------------------------------------------------------------------
// bf16-split NT GEMM via mma.sync (HMMA): C[128,128] tile = A[M,K] * B[N,K]^T
// MODE 1: C = GELU(A*B^T + bias)                 -> g_h1
// MODE 2: per-batch expert (+emb / passthrough)  -> g_h2
// MODE 3: C = A*B^T + bias + residual            -> g_pre
// 512 threads (4x4 warps, 32x32 warp tile), BK=64, register-prefetch pipeline.
// SMEM: Ah(16K) Al(16K) Bh(16K) Bl(16K) = 64KB, SW128-style XOR swizzle.
// ---------------------------------------------------------------------------
#define SMEM_BYTES 65536

template <int MODE>
__global__ __launch_bounds__(512, 1)
void hmma_gemm(const float* __restrict__ Aext,
               const float* __restrict__ Bw,
               const float* __restrict__ bias,
               const float* __restrict__ extra) {
    constexpr int K  = (MODE == 1) ? Dv : Av;
    constexpr int N  = (MODE == 3) ? Dv : Av;
    constexpr int NC = K / 64;

    extern __shared__ char sm[];
    const uint32_t sbase = smem_u32(sm);

    const int tid  = threadIdx.x;
    const int lane = tid & 31;
    const int wid  = tid >> 5;
    const int wm   = wid & 3;     // warp row (M)
    const int wn   = wid >> 2;    // warp col (N)

    int m0;
    const int n0 = blockIdx.x * 128;
    const float* Ap;
    const float* Bp = Bw;
    const float* biasp = bias;
    const float* embp = nullptr;
    float* Cp;
    int valid = 1;
    if (MODE == 1) {
        m0 = blockIdx.y * 128; Ap = Aext; Cp = g_h1;
    } else if (MODE == 2) {
        const int b = blockIdx.z;
        const int e = g_idx[b];
        valid = g_valid[b];
        m0 = b * Sv + blockIdx.y * 128;
        Ap = g_h1;
        Bp = Bw + (size_t)e * Av * Av;
        biasp = bias + (size_t)e * Av;
        embp = extra + (size_t)e * Av;
        Cp = g_h2;
    } else {
        m0 = blockIdx.y * 128; Ap = g_h2; Cp = g_pre;
    }

    const float* ArowBase = Ap + (size_t)m0 * K;
    const float* BrowBase = Bp + (size_t)n0 * K;

    // per-thread GMEM->SMEM coords: 2048 float4 per operand tile, 4 per thread
    int lr[4], lc[4];
    uint32_t soff[4];
#pragma unroll
    for (int i = 0; i < 4; i++) {
        const int idx = tid + i * 512;
        lr[i] = idx >> 4;
        lc[i] = (idx & 15) * 4;
        soff[i] = (uint32_t)(lr[i] * 128) +
                  (uint32_t)((lc[i] * 2) ^ ((lr[i] & 7) << 4));
    }

    float4 pA[4], pB[4];
#pragma unroll
    for (int i = 0; i < 4; i++) {
        pA[i] = *(const float4*)(ArowBase + (size_t)lr[i] * K + lc[i]);
        pB[i] = *(const float4*)(BrowBase + (size_t)lr[i] * K + lc[i]);
    }

    float acc[2][4][4];
#pragma unroll
    for (int mt = 0; mt < 2; mt++)
#pragma unroll
        for (int nt = 0; nt < 4; nt++)
#pragma unroll
            for (int q = 0; q < 4; q++) acc[mt][nt][q] = 0.f;

    for (int c = 0; c < NC; c++) {
        // stage prefetched chunk into SMEM (hi/lo split)
#pragma unroll
        for (int i = 0; i < 4; i++) {
            split_store(sm,          sm + 16384, soff[i], pA[i]);
            split_store(sm + 32768,  sm + 49152, soff[i], pB[i]);
        }
        __syncthreads();

        // prefetch next chunk
        if (c + 1 < NC) {
            const int k0 = (c + 1) * 64;
#pragma unroll
            for (int i = 0; i < 4; i++) {
                pA[i] = *(const float4*)(ArowBase + (size_t)lr[i] * K + k0 + lc[i]);
                pB[i] = *(const float4*)(BrowBase + (size_t)lr[i] * K + k0 + lc[i]);
            }
        }

        // compute chunk: 4 k16 steps x 3 split passes
#pragma unroll
        for (int k16 = 0; k16 < 4; k16++) {
            uint32_t ah[2][4], al[2][4], bh[2][4], bl[2][4];
#pragma unroll
            for (int mt = 0; mt < 2; mt++) {
                const int row = wm * 32 + mt * 16 + (lane & 15);
                const int kc  = k16 * 16 + (lane >> 4) * 8;
                const uint32_t off = (uint32_t)(row * 128) +
                                     (uint32_t)((kc * 2) ^ ((row & 7) << 4));
                LDSM4(ah[mt], sbase + off);
                LDSM4(al[mt], sbase + 16384u + off);
            }
#pragma unroll
            for (int p = 0; p < 2; p++) {
                const int g    = lane >> 3;
                const int nrow = wn * 32 + p * 16 + (g >> 1) * 8 + (lane & 7);
                const int kc   = k16 * 16 + (g & 1) * 8;
                const uint32_t off = (uint32_t)(nrow * 128) +
                                     (uint32_t)((kc * 2) ^ ((nrow & 7) << 4));
                LDSM4(bh[p], sbase + 32768u + off);
                LDSM4(bl[p], sbase + 49152u + off);
            }
#pragma unroll
            for (int mt = 0; mt < 2; mt++)
#pragma unroll
                for (int nt = 0; nt < 4; nt++) {
                    const uint32_t h0 = bh[nt >> 1][(nt & 1) * 2];
                    const uint32_t h1 = bh[nt >> 1][(nt & 1) * 2 + 1];
                    const uint32_t l0 = bl[nt >> 1][(nt & 1) * 2];
                    const uint32_t l1 = bl[nt >> 1][(nt & 1) * 2 + 1];
                    MMA_OP(acc[mt][nt], ah[mt], h0, h1);   // hi*hi
                    MMA_OP(acc[mt][nt], ah[mt], l0, l1);   // hi*lo
                    MMA_OP(acc[mt][nt], al[mt], h0, h1);   // lo*hi
                }
        }
        __syncthreads();
    }

    // ---- epilogue: C frag (mt, nt, half): rows m+lane/4 (+8), cols nt*8+2*(lane&3)
#pragma unroll
    for (int mt = 0; mt < 2; mt++)
#pragma unroll
        for (int half = 0; half < 2; half++) {
            const int r = m0 + wm * 32 + mt * 16 + (lane >> 2) + half * 8;
#pragma unroll
            for (int nt = 0; nt < 4; nt++) {
                const int col = n0 + wn * 32 + nt * 8 + (lane & 3) * 2;
                float vx = acc[mt][nt][half * 2];
                float vy = acc[mt][nt][half * 2 + 1];
                if (MODE == 1) {
                    const float2 bi = *(const float2*)(bias + col);
                    vx = gelu_exact(vx + bi.x);
                    vy = gelu_exact(vy + bi.y);
                } else if (MODE == 2) {
                    if (valid) {
                        const float2 bi = *(const float2*)(biasp + col);
                        vx += bi.x; vy += bi.y;
                    } else {
                        const float2 pv = *(const float2*)(g_h1 + (size_t)r * Av + col);
                        vx = pv.x; vy = pv.y;
                    }
                    const float2 em = *(const float2*)(embp + col);
                    vx += em.x; vy += em.y;
                } else {
                    const float2 bi = *(const float2*)(bias + col);
                    const float2 rs = *(const float2*)(extra + (size_t)r * Dv + col);
                    vx += bi.x + rs.x;
                    vy += bi.y + rs.y;
                }
                *(float2*)(Cp + (size_t)r * N + col) = make_float2(vx, vy);
            }
        }
}

// ---------------------------------------------------------------------------
// LayerNorm over D=1024 (one 256-thread block per row, 4 elems/thread)
// ---------------------------------------------------------------------------
__global__ __launch_bounds__(256)
void ln_kernel(const float* __restrict__ gamma,
               const float* __restrict__ beta,
               float* __restrict__ out) {
    const int row = blockIdx.x;
    const int t = threadIdx.x;
    const float4 v = *(const float4*)(g_pre + (size_t)row * Dv + t * 4);

    __shared__ float red1[8];
    __shared__ float red2[8];

    float s = v.x + v.y + v.z + v.w;
#pragma unroll
    for (int o = 16; o; o >>= 1) s += __shfl_xor_sync(0xFFFFFFFFu, s, o);
    if ((t & 31) == 0) red1[t >> 5] = s;
    __syncthreads();
    float tot = 0.f;
#pragma unroll
    for (int i = 0; i < 8; i++) tot += red1[i];
    const float mu = tot * (1.0f / Dv);

    const float dx = v.x - mu, dy = v.y - mu, dz = v.z - mu, dw = v.w - mu;
    float s2 = dx * dx + dy * dy + dz * dz + dw * dw;
#pragma unroll
    for (int o = 16; o; o >>= 1) s2 += __shfl_xor_sync(0xFFFFFFFFu, s2, o);
    if ((t & 31) == 0) red2[t >> 5] = s2;
    __syncthreads();
    float tot2 = 0.f;
#pragma unroll
    for (int i = 0; i < 8; i++) tot2 += red2[i];
    const float inv = rsqrtf(tot2 * (1.0f / Dv) + 1e-5f);

    const int c = t * 4;
    const float4 gm = *(const float4*)(gamma + c);
    const float4 bt = *(const float4*)(beta + c);
    float4 o;
    o.x = dx * inv * gm.x + bt.x;
    o.y = dy * inv * gm.y + bt.y;
    o.z = dz * inv * gm.z + bt.z;
    o.w = dw * inv * gm.w + bt.w;
    *(float4*)(out + (size_t)row * Dv + c) = o;
}

// ---------------------------------------------------------------------------
extern "C" void kernel_launch(void* const* d_in, const int* in_sizes, int n_in,
                              void* d_out, int out_size) {
    const float* hidden     = (const float*)d_in[0];
    const int*   dom        = (const int*)d_in[1];
    const float* down_W     = (const float*)d_in[2];
    const float* down_b     = (const float*)d_in[3];
    const float* up_W       = (const float*)d_in[4];
    const float* up_b       = (const float*)d_in[5];
    const float* expert_W   = (const float*)d_in[6];
    const float* expert_b   = (const float*)d_in[7];
    const float* domain_emb = (const float*)d_in[8];
    const float* gamma      = (const float*)d_in[9];
    const float* beta       = (const float*)d_in[10];
    float* out = (float*)d_out;

    cudaFuncSetAttribute(hmma_gemm<1>, cudaFuncAttributeMaxDynamicSharedMemorySize, SMEM_BYTES);
    cudaFuncSetAttribute(hmma_gemm<2>, cudaFuncAttributeMaxDynamicSharedMemorySize, SMEM_BYTES);
    cudaFuncSetAttribute(hmma_gemm<3>, cudaFuncAttributeMaxDynamicSharedMemorySize, SMEM_BYTES);

    prep_ids<<<1, 1>>>(dom);

    // Stage 1: down-proj + GELU   (M=32768, N=256,  K=1024)
    hmma_gemm<1><<<dim3(Av / 128, Mrows / 128), 512, SMEM_BYTES>>>(hidden, down_W, down_b, nullptr);
    // Stage 2: per-batch expert   (per batch M=1024, N=256, K=256)
    hmma_gemm<2><<<dim3(Av / 128, Sv / 128, Bv), 512, SMEM_BYTES>>>(nullptr, expert_W, expert_b, domain_emb);
    // Stage 3: up-proj + residual (M=32768, N=1024, K=256)
    hmma_gemm<3><<<dim3(Dv / 128, Mrows / 128), 512, SMEM_BYTES>>>(nullptr, up_W, up_b, hidden);
    // Stage 4: LayerNorm
    ln_kernel<<<Mrows, 256>>>(gamma, beta, out);
}

// round 4
// speedup vs baseline: 2.4479x; 1.0189x over previous
#include <cuda_runtime.h>
#include <cuda_bf16.h>
#include <math.h>
#include <stdint.h>

// Problem dims (fixed)
#define Bv 32
#define Sv 1024
#define Dv 1024
#define Av 256
#define Ev 16
#define Mrows (Bv * Sv)   // 32768

// ---------------------------------------------------------------------------
// Persistent scratch (no cudaMalloc allowed)
// ---------------------------------------------------------------------------
__device__ float g_pre[(size_t)Mrows * Dv];           // pre-LN fp32
__device__ __nv_bfloat16 g_h1h[(size_t)Mrows * Av];   // stage1 out hi
__device__ __nv_bfloat16 g_h1l[(size_t)Mrows * Av];   // stage1 out lo
__device__ __nv_bfloat16 g_h2h[(size_t)Mrows * Av];   // stage2 out hi
__device__ __nv_bfloat16 g_h2l[(size_t)Mrows * Av];   // stage2 out lo
__device__ __nv_bfloat16 g_dwh[Av * Dv], g_dwl[Av * Dv];        // down_W split
__device__ __nv_bfloat16 g_uwh[Dv * Av], g_uwl[Dv * Av];        // up_W split
__device__ __nv_bfloat16 g_ewh[Ev * Av * Av], g_ewl[Ev * Av * Av]; // expert_W split
__device__ int g_idx[Bv];
__device__ int g_valid[Bv];

// ---------------------------------------------------------------------------
__device__ __forceinline__ uint32_t smem_u32(const void* p) {
    uint32_t a;
    asm("{ .reg .u64 t; cvta.to.shared.u64 t, %1; cvt.u32.u64 %0, t; }" : "=r"(a) : "l"(p));
    return a;
}
#define LDSM4(r, addr) \
    asm volatile("ldmatrix.sync.aligned.m8n8.x4.shared.b16 {%0,%1,%2,%3}, [%4];" \
        : "=r"((r)[0]), "=r"((r)[1]), "=r"((r)[2]), "=r"((r)[3]) : "r"(addr))
#define MMA_OP(d, a, b0, b1) \
    asm volatile("mma.sync.aligned.m16n8k16.row.col.f32.bf16.bf16.f32 " \
        "{%0,%1,%2,%3}, {%4,%5,%6,%7}, {%8,%9}, {%0,%1,%2,%3};" \
        : "+f"((d)[0]), "+f"((d)[1]), "+f"((d)[2]), "+f"((d)[3]) \
        : "r"((a)[0]), "r"((a)[1]), "r"((a)[2]), "r"((a)[3]), "r"(b0), "r"(b1))
#define CP16(dst, src) \
    asm volatile("cp.async.cg.shared.global [%0], [%1], 16;" :: "r"(dst), "l"(src))
#define CPCOMMIT() asm volatile("cp.async.commit_group;" ::: "memory")
#define CPWAIT0()  asm volatile("cp.async.wait_group 0;" ::: "memory")

// ---------------------------------------------------------------------------
// domain_id may arrive as int32 or int64. Detect and normalize.
// ---------------------------------------------------------------------------
__global__ void prep_ids(const int* __restrict__ p) {
    bool is64 = true;
    for (int k = 0; k < 16; k++) {
        int hi = p[2 * k + 1];
        if (hi != 0 && hi != -1) { is64 = false; break; }
    }
    for (int b = 0; b < Bv; b++) {
        long long v;
        if (is64) {
            unsigned int lo = (unsigned int)p[2 * b];
            int hi = p[2 * b + 1];
            v = ((long long)hi << 32) | (long long)lo;
        } else {
            v = p[b];
        }
        g_valid[b] = (v >= 0 && v < Ev) ? 1 : 0;
        long long c = v < 0 ? 0 : (v > (Ev - 1) ? (Ev - 1) : v);
        g_idx[b] = (int)c;
    }
}

// Split fp32 array into bf16 hi/lo arrays (weights, done once per launch)
__global__ void split_w(const float* __restrict__ src,
                        __nv_bfloat16* __restrict__ H,
                        __nv_bfloat16* __restrict__ L, int n) {
    for (int i = blockIdx.x * blockDim.x + threadIdx.x; i < n;
         i += gridDim.x * blockDim.x) {
        float v = src[i];
        __nv_bfloat16 h = __float2bfloat16(v);
        H[i] = h;
        L[i] = __float2bfloat16(v - __bfloat162float(h));
    }
}

__device__ __forceinline__ float gelu_exact(float v) {
    return 0.5f * v * (1.0f + erff(v * 0.70710678118654752440f));
}

// Split fp32 float4 into hi/lo bf16 pairs and store 8B each (swizzle-safe).
__device__ __forceinline__ void split_store(char* hi_base, char* lo_base,
                                            uint32_t off, float4 v) {
    __nv_bfloat162 h0 = __floats2bfloat162_rn(v.x, v.y);
    __nv_bfloat162 h1 = __floats2bfloat162_rn(v.z, v.w);
    float2 f0 = __bfloat1622float2(h0);
    float2 f1 = __bfloat1622float2(h1);
    __nv_bfloat162 l0 = __floats2bfloat162_rn(v.x - f0.x, v.y - f0.y);
    __nv_bfloat162 l1 = __floats2bfloat162_rn(v.z - f1.x, v.w - f1.y);
    *(uint2*)(hi_base + off) = make_uint2(*(uint32_t*)&h0, *(uint32_t*)&h1);
    *(uint2*)(lo_base + off) = make_uint2(*(uint32_t*)&l0, *(uint32_t*)&l1);
}

// Epilogue split-write of a float2 into hi/lo bf16 arrays.
__device__ __forceinline__ void ep_split(__nv_bfloat16* H, __nv_bfloat16* L,
                                         size_t off, float x, float y) {
    __nv_bfloat162 h = __floats2bfloat162_rn(x, y);
    float2 hf = __bfloat1622float2(h);
    __nv_bfloat162 l = __floats2bfloat162_rn(x - hf.x, y - hf.y);
    *(uint32_t*)(H + off) = *(uint32_t*)&h;
    *(uint32_t*)(L + off) = *(uint32_t*)&l;
}

// cp.async loader: one 128x64 bf16 chunk (hi+lo) into swizzled SMEM.
// 512 threads, 2 lines of 16B each per half per thread.
__device__ __forceinline__ void load_presplit(uint32_t dstHi, uint32_t dstLo,
                                              const __nv_bfloat16* __restrict__ hi,
                                              const __nv_bfloat16* __restrict__ lo,
                                              int tid, int K, int k0) {
#pragma unroll
    for (int i = 0; i < 2; i++) {
        const int idx = tid + i * 512;
        const int row = idx >> 3;
        const int c8 = idx & 7;
        const uint32_t off = (uint32_t)(row * 128) +
                             (uint32_t)((c8 * 16) ^ ((row & 7) << 4));
        const size_t g = (size_t)row * K + k0 + c8 * 8;
        CP16(dstHi + off, hi + g);
        CP16(dstLo + off, lo + g);
    }
}

// ---------------------------------------------------------------------------
// bf16-split NT GEMM via mma.sync: C[128,128] tile = A[M,K] * B[N,K]^T
// 3 MMA passes (hi*hi + hi*lo + lo*hi), fp32 accum.
// MODE 1: A = hidden fp32 (runtime split), B = down_W presplit; GELU -> g_h1h/l
// MODE 2: A = g_h1 presplit, B = expert_W[e] presplit; +bias/pass + emb -> g_h2h/l
// MODE 3: A = g_h2 presplit, B = up_W presplit; +bias+residual -> g_pre fp32
// 512 threads (4x4 warps, 32x32 warp tile), BK=64, double-buffered cp.async.
// SMEM per stage: Ah Al Bh Bl (16KB each) = 64KB; 2 stages = 128KB.
// ---------------------------------------------------------------------------
#define STAGE_B 65536
#define SMEM_BYTES (2 * STAGE_B)

template <int MODE>
__global__ __launch_bounds__(512, 1)
void hmma_gemm(const float* __restrict__ Afp,
               const float* __restrict__ bias,
               const float* __restrict__ extra) {
    constexpr int K  = (MODE == 1) ? Dv : Av;
    constexpr int N  = (MODE == 3) ? Dv : Av;
    constexpr int NC = K / 64;

    extern __shared__ char sm[];
    const uint32_t sbase = smem_u32(sm);

    const int tid  = threadIdx.x;
    const int lane = tid & 31;
    const int wid  = tid >> 5;
    const int wm   = wid & 3;
    const int wn   = wid >> 2;

    int m0;
    const int n0 = blockIdx.x * 128;
    const __nv_bfloat16 *Ah = nullptr, *Al = nullptr, *Bh, *Bl;
    const float* biasp = bias;
    const float* embp = nullptr;
    int valid = 1;
    if (MODE == 1) {
        m0 = blockIdx.y * 128;
        Bh = g_dwh; Bl = g_dwl;
    } else if (MODE == 2) {
        const int b = blockIdx.z;
        const int e = g_idx[b];
        valid = g_valid[b];
        m0 = b * Sv + blockIdx.y * 128;
        Ah = g_h1h; Al = g_h1l;
        Bh = g_ewh + (size_t)e * Av * Av;
        Bl = g_ewl + (size_t)e * Av * Av;
        biasp = bias + (size_t)e * Av;
        embp = extra + (size_t)e * Av;
    } else {
        m0 = blockIdx.y * 128;
        Ah = g_h2h; Al = g_h2l;
        Bh = g_uwh; Bl = g_uwl;
    }

    const float* ArowF = (MODE == 1) ? (Afp + (size_t)m0 * K) : nullptr;
    const __nv_bfloat16* ArowH = (MODE != 1) ? (Ah + (size_t)m0 * K) : nullptr;
    const __nv_bfloat16* ArowL = (MODE != 1) ? (Al + (size_t)m0 * K) : nullptr;
    const __nv_bfloat16* BrowH = Bh + (size_t)n0 * K;
    const __nv_bfloat16* BrowL = Bl + (size_t)n0 * K;

    // MODE1 A register-split coords
    int lr[4], lc[4];
    uint32_t soff[4];
    float4 pA[4];
    if (MODE == 1) {
#pragma unroll
        for (int i = 0; i < 4; i++) {
            const int idx = tid + i * 512;
            lr[i] = idx >> 4;
            lc[i] = (idx & 15) * 4;
            soff[i] = (uint32_t)(lr[i] * 128) +
                      (uint32_t)((lc[i] * 2) ^ ((lr[i] & 7) << 4));
            pA[i] = *(const float4*)(ArowF + (size_t)lr[i] * K + lc[i]);
        }
    }

    // Prologue: issue chunk 0 copies
    {
        const uint32_t sb = sbase;
        if (MODE != 1) load_presplit(sb, sb + 16384u, ArowH, ArowL, tid, K, 0);
        load_presplit(sb + 32768u, sb + 49152u, BrowH, BrowL, tid, K, 0);
        CPCOMMIT();
    }

    float acc[2][4][4];
#pragma unroll
    for (int mt = 0; mt < 2; mt++)
#pragma unroll
        for (int nt = 0; nt < 4; nt++)
#pragma unroll
            for (int q = 0; q < 4; q++) acc[mt][nt][q] = 0.f;

    for (int c = 0; c < NC; c++) {
        const int s = c & 1;
        const uint32_t sb = sbase + s * STAGE_B;

        if (MODE == 1) {
            char* smc = sm + s * STAGE_B;
#pragma unroll
            for (int i = 0; i < 4; i++)
                split_store(smc, smc + 16384, soff[i], pA[i]);
        }
        CPWAIT0();
        __syncthreads();

        if (c + 1 < NC) {
            const uint32_t nb = sbase + (s ^ 1) * STAGE_B;
            const int k0 = (c + 1) * 64;
            if (MODE != 1)
                load_presplit(nb, nb + 16384u, ArowH, ArowL, tid, K, k0);
            load_presplit(nb + 32768u, nb + 49152u, BrowH, BrowL, tid, K, k0);
            CPCOMMIT();
            if (MODE == 1) {
#pragma unroll
                for (int i = 0; i < 4; i++)
                    pA[i] = *(const float4*)(ArowF + (size_t)lr[i] * K + k0 + lc[i]);
            }
        }

        // compute chunk: 4 k16 steps x 3 split passes
#pragma unroll
        for (int k16 = 0; k16 < 4; k16++) {
            uint32_t ah[2][4], al[2][4], bh[2][4], bl[2][4];
#pragma unroll
            for (int mt = 0; mt < 2; mt++) {
                const int row = wm * 32 + mt * 16 + (lane & 15);
                const int kc  = k16 * 16 + (lane >> 4) * 8;
                const uint32_t off = (uint32_t)(row * 128) +
                                     (uint32_t)((kc * 2) ^ ((row & 7) << 4));
                LDSM4(ah[mt], sb + off);
                LDSM4(al[mt], sb + 16384u + off);
            }
#pragma unroll
            for (int p = 0; p < 2; p++) {
                const int g    = lane >> 3;
                const int nrow = wn * 32 + p * 16 + (g >> 1) * 8 + (lane & 7);
                const int kc   = k16 * 16 + (g & 1) * 8;
                const uint32_t off = (uint32_t)(nrow * 128) +
                                     (uint32_t)((kc * 2) ^ ((nrow & 7) << 4));
                LDSM4(bh[p], sb + 32768u + off);
                LDSM4(bl[p], sb + 49152u + off);
            }
#pragma unroll
            for (int mt = 0; mt < 2; mt++)
#pragma unroll
                for (int nt = 0; nt < 4; nt++) {
                    const uint32_t h0 = bh[nt >> 1][(nt & 1) * 2];
                    const uint32_t h1 = bh[nt >> 1][(nt & 1) * 2 + 1];
                    const uint32_t l0 = bl[nt >> 1][(nt & 1) * 2];
                    const uint32_t l1 = bl[nt >> 1][(nt & 1) * 2 + 1];
                    MMA_OP(acc[mt][nt], ah[mt], h0, h1);   // hi*hi
                    MMA_OP(acc[mt][nt], ah[mt], l0, l1);   // hi*lo
                    MMA_OP(acc[mt][nt], al[mt], h0, h1);   // lo*hi
                }
        }
        __syncthreads();
    }

    // ---- epilogue ----
#pragma unroll
    for (int mt = 0; mt < 2; mt++)
#pragma unroll
        for (int half = 0; half < 2; half++) {
            const int r = m0 + wm * 32 + mt * 16 + (lane >> 2) + half * 8;
#pragma unroll
            for (int nt = 0; nt < 4; nt++) {
                const int col = n0 + wn * 32 + nt * 8 + (lane & 3) * 2;
                float vx = acc[mt][nt][half * 2];
                float vy = acc[mt][nt][half * 2 + 1];
                if (MODE == 1) {
                    const float2 bi = *(const float2*)(bias + col);
                    vx = gelu_exact(vx + bi.x);
                    vy = gelu_exact(vy + bi.y);
                    ep_split(g_h1h, g_h1l, (size_t)r * Av + col, vx, vy);
                } else if (MODE == 2) {
                    if (valid) {
                        const float2 bi = *(const float2*)(biasp + col);
                        vx += bi.x; vy += bi.y;
                    } else {
                        const size_t o = (size_t)r * Av + col;
                        uint32_t ph = *(const uint32_t*)(g_h1h + o);
                        uint32_t pl = *(const uint32_t*)(g_h1l + o);
                        float2 fh = __bfloat1622float2(*(__nv_bfloat162*)&ph);
                        float2 fl = __bfloat1622float2(*(__nv_bfloat162*)&pl);
                        vx = fh.x + fl.x;
                        vy = fh.y + fl.y;
                    }
                    const float2 em = *(const float2*)(embp + col);
                    vx += em.x; vy += em.y;
                    ep_split(g_h2h, g_h2l, (size_t)r * Av + col, vx, vy);
                } else {
                    const float2 bi = *(const float2*)(bias + col);
                    const float2 rs = *(const float2*)(extra + (size_t)r * Dv + col);
                    vx += bi.x + rs.x;
                    vy += bi.y + rs.y;
                    *(float2*)(g_pre + (size_t)r * N + col) = make_float2(vx, vy);
                }
            }
        }
}

// ---------------------------------------------------------------------------
// LayerNorm over D=1024 (one 256-thread block per row, 4 elems/thread)
// ---------------------------------------------------------------------------
__global__ __launch_bounds__(256)
void ln_kernel(const float* __restrict__ gamma,
               const float* __restrict__ beta,
               float* __restrict__ out) {
    const int row = blockIdx.x;
    const int t = threadIdx.x;
    const float4 v = *(const float4*)(g_pre + (size_t)row * Dv + t * 4);

    __shared__ float red1[8];
    __shared__ float red2[8];

    float s = v.x + v.y + v.z + v.w;
#pragma unroll
    for (int o = 16; o; o >>= 1) s += __shfl_xor_sync(0xFFFFFFFFu, s, o);
    if ((t & 31) == 0) red1[t >> 5] = s;
    __syncthreads();
    float tot = 0.f;
#pragma unroll
    for (int i = 0; i < 8; i++) tot += red1[i];
    const float mu = tot * (1.0f / Dv);

    const float dx = v.x - mu, dy = v.y - mu, dz = v.z - mu, dw = v.w - mu;
    float s2 = dx * dx + dy * dy + dz * dz + dw * dw;
#pragma unroll
    for (int o = 16; o; o >>= 1) s2 += __shfl_xor_sync(0xFFFFFFFFu, s2, o);
    if ((t & 31) == 0) red2[t >> 5] = s2;
    __syncthreads();
    float tot2 = 0.f;
#pragma unroll
    for (int i = 0; i < 8; i++) tot2 += red2[i];
    const float inv = rsqrtf(tot2 * (1.0f / Dv) + 1e-5f);

    const int c = t * 4;
    const float4 gm = *(const float4*)(gamma + c);
    const float4 bt = *(const float4*)(beta + c);
    float4 o;
    o.x = dx * inv * gm.x + bt.x;
    o.y = dy * inv * gm.y + bt.y;
    o.z = dz * inv * gm.z + bt.z;
    o.w = dw * inv * gm.w + bt.w;
    *(float4*)(out + (size_t)row * Dv + c) = o;
}

// ---------------------------------------------------------------------------
extern "C" void kernel_launch(void* const* d_in, const int* in_sizes, int n_in,
                              void* d_out, int out_size) {
    const float* hidden     = (const float*)d_in[0];
    const int*   dom        = (const int*)d_in[1];
    const float* down_W     = (const float*)d_in[2];
    const float* down_b     = (const float*)d_in[3];
    const float* up_W       = (const float*)d_in[4];
    const float* up_b       = (const float*)d_in[5];
    const float* expert_W   = (const float*)d_in[6];
    const float* expert_b   = (const float*)d_in[7];
    const float* domain_emb = (const float*)d_in[8];
    const float* gamma      = (const float*)d_in[9];
    const float* beta       = (const float*)d_in[10];
    float* out = (float*)d_out;

    cudaFuncSetAttribute(hmma_gemm<1>, cudaFuncAttributeMaxDynamicSharedMemorySize, SMEM_BYTES);
    cudaFuncSetAttribute(hmma_gemm<2>, cudaFuncAttributeMaxDynamicSharedMemorySize, SMEM_BYTES);
    cudaFuncSetAttribute(hmma_gemm<3>, cudaFuncAttributeMaxDynamicSharedMemorySize, SMEM_BYTES);

    prep_ids<<<1, 1>>>(dom);

    // one-time weight splits (device globals)
    __nv_bfloat16 *dwh, *dwl, *uwh, *uwl, *ewh, *ewl;
    cudaGetSymbolAddress((void**)&dwh, g_dwh);
    cudaGetSymbolAddress((void**)&dwl, g_dwl);
    cudaGetSymbolAddress((void**)&uwh, g_uwh);
    cudaGetSymbolAddress((void**)&uwl, g_uwl);
    cudaGetSymbolAddress((void**)&ewh, g_ewh);
    cudaGetSymbolAddress((void**)&ewl, g_ewl);
    split_w<<<256, 512>>>(down_W, dwh, dwl, Av * Dv);
    split_w<<<256, 512>>>(up_W, uwh, uwl, Dv * Av);
    split_w<<<512, 512>>>(expert_W, ewh, ewl, Ev * Av * Av);

    // Stage 1: down-proj + GELU   (M=32768, N=256,  K=1024)
    hmma_gemm<1><<<dim3(Av / 128, Mrows / 128), 512, SMEM_BYTES>>>(hidden, down_b, nullptr);
    // Stage 2: per-batch expert   (per batch M=1024, N=256, K=256)
    hmma_gemm<2><<<dim3(Av / 128, Sv / 128, Bv), 512, SMEM_BYTES>>>(nullptr, expert_b, domain_emb);
    // Stage 3: up-proj + residual (M=32768, N=1024, K=256)
    hmma_gemm<3><<<dim3(Dv / 128, Mrows / 128), 512, SMEM_BYTES>>>(nullptr, up_b, hidden);
    // Stage 4: LayerNorm
    ln_kernel<<<Mrows, 256>>>(gamma, beta, out);
}

// round 5
// speedup vs baseline: 2.6344x; 1.0762x over previous
#include <cuda_runtime.h>
#include <cuda_bf16.h>
#include <math.h>
#include <stdint.h>

// Problem dims (fixed)
#define Bv 32
#define Sv 1024
#define Dv 1024
#define Av 256
#define Ev 16
#define Mrows (Bv * Sv)   // 32768

// ---------------------------------------------------------------------------
// Persistent scratch (no cudaMalloc allowed)
// ---------------------------------------------------------------------------
__device__ float g_pre[(size_t)Mrows * Dv];           // pre-LN fp32
__device__ __nv_bfloat16 g_h1h[(size_t)Mrows * Av];   // stage1 out hi
__device__ __nv_bfloat16 g_h1l[(size_t)Mrows * Av];   // stage1 out lo
__device__ __nv_bfloat16 g_h2h[(size_t)Mrows * Av];   // stage2 out hi
__device__ __nv_bfloat16 g_h2l[(size_t)Mrows * Av];   // stage2 out lo
__device__ __nv_bfloat16 g_dwh[Av * Dv], g_dwl[Av * Dv];        // down_W split
__device__ __nv_bfloat16 g_uwh[Dv * Av], g_uwl[Dv * Av];        // up_W split
__device__ __nv_bfloat16 g_ewh[Ev * Av * Av], g_ewl[Ev * Av * Av]; // expert_W split
__device__ int g_idx[Bv];
__device__ int g_valid[Bv];

// ---------------------------------------------------------------------------
__device__ __forceinline__ uint32_t smem_u32(const void* p) {
    uint32_t a;
    asm("{ .reg .u64 t; cvta.to.shared.u64 t, %1; cvt.u32.u64 %0, t; }" : "=r"(a) : "l"(p));
    return a;
}
#define LDSM4(r, addr) \
    asm volatile("ldmatrix.sync.aligned.m8n8.x4.shared.b16 {%0,%1,%2,%3}, [%4];" \
        : "=r"((r)[0]), "=r"((r)[1]), "=r"((r)[2]), "=r"((r)[3]) : "r"(addr))
#define MMA_OP(d, a, b0, b1) \
    asm volatile("mma.sync.aligned.m16n8k16.row.col.f32.bf16.bf16.f32 " \
        "{%0,%1,%2,%3}, {%4,%5,%6,%7}, {%8,%9}, {%0,%1,%2,%3};" \
        : "+f"((d)[0]), "+f"((d)[1]), "+f"((d)[2]), "+f"((d)[3]) \
        : "r"((a)[0]), "r"((a)[1]), "r"((a)[2]), "r"((a)[3]), "r"(b0), "r"(b1))
#define CP16(dst, src) \
    asm volatile("cp.async.cg.shared.global [%0], [%1], 16;" :: "r"(dst), "l"(src))
#define CPCOMMIT() asm volatile("cp.async.commit_group;" ::: "memory")
#define CPWAIT0()  asm volatile("cp.async.wait_group 0;" ::: "memory")

// ---------------------------------------------------------------------------
// domain_id may arrive as int32 or int64. Detect and normalize.
// ---------------------------------------------------------------------------
__global__ void prep_ids(const int* __restrict__ p) {
    bool is64 = true;
    for (int k = 0; k < 16; k++) {
        int hi = p[2 * k + 1];
        if (hi != 0 && hi != -1) { is64 = false; break; }
    }
    for (int b = 0; b < Bv; b++) {
        long long v;
        if (is64) {
            unsigned int lo = (unsigned int)p[2 * b];
            int hi = p[2 * b + 1];
            v = ((long long)hi << 32) | (long long)lo;
        } else {
            v = p[b];
        }
        g_valid[b] = (v >= 0 && v < Ev) ? 1 : 0;
        long long c = v < 0 ? 0 : (v > (Ev - 1) ? (Ev - 1) : v);
        g_idx[b] = (int)c;
    }
}

// Split fp32 array into bf16 hi/lo arrays (weights, done once per launch)
__global__ void split_w(const float* __restrict__ src,
                        __nv_bfloat16* __restrict__ H,
                        __nv_bfloat16* __restrict__ L, int n) {
    for (int i = blockIdx.x * blockDim.x + threadIdx.x; i < n;
         i += gridDim.x * blockDim.x) {
        float v = src[i];
        __nv_bfloat16 h = __float2bfloat16(v);
        H[i] = h;
        L[i] = __float2bfloat16(v - __bfloat162float(h));
    }
}

__device__ __forceinline__ float gelu_exact(float v) {
    return 0.5f * v * (1.0f + erff(v * 0.70710678118654752440f));
}

// Split fp32 float4 into hi/lo bf16 pairs and store 8B each (swizzle-safe).
__device__ __forceinline__ void split_store(char* hi_base, char* lo_base,
                                            uint32_t off, float4 v) {
    __nv_bfloat162 h0 = __floats2bfloat162_rn(v.x, v.y);
    __nv_bfloat162 h1 = __floats2bfloat162_rn(v.z, v.w);
    float2 f0 = __bfloat1622float2(h0);
    float2 f1 = __bfloat1622float2(h1);
    __nv_bfloat162 l0 = __floats2bfloat162_rn(v.x - f0.x, v.y - f0.y);
    __nv_bfloat162 l1 = __floats2bfloat162_rn(v.z - f1.x, v.w - f1.y);
    *(uint2*)(hi_base + off) = make_uint2(*(uint32_t*)&h0, *(uint32_t*)&h1);
    *(uint2*)(lo_base + off) = make_uint2(*(uint32_t*)&l0, *(uint32_t*)&l1);
}

// Epilogue split-write of a float2 into hi/lo bf16 arrays.
__device__ __forceinline__ void ep_split(__nv_bfloat16* H, __nv_bfloat16* L,
                                         size_t off, float x, float y) {
    __nv_bfloat162 h = __floats2bfloat162_rn(x, y);
    float2 hf = __bfloat1622float2(h);
    __nv_bfloat162 l = __floats2bfloat162_rn(x - hf.x, y - hf.y);
    *(uint32_t*)(H + off) = *(uint32_t*)&h;
    *(uint32_t*)(L + off) = *(uint32_t*)&l;
}

// cp.async loader: ROWS x 64 bf16 chunk (hi+lo) into swizzled SMEM.
// 512 threads; ROWS/64 lines of 16B per half per thread.
template <int ROWS>
__device__ __forceinline__ void load_presplit(uint32_t dstHi, uint32_t dstLo,
                                              const __nv_bfloat16* __restrict__ hi,
                                              const __nv_bfloat16* __restrict__ lo,
                                              int tid, int K, int k0) {
#pragma unroll
    for (int i = 0; i < ROWS / 64; i++) {
        const int idx = tid + i * 512;
        const int row = idx >> 3;
        const int c8 = idx & 7;
        const uint32_t off = (uint32_t)(row * 128) +
                             (uint32_t)((c8 * 16) ^ ((row & 7) << 4));
        const size_t g = (size_t)row * K + k0 + c8 * 8;
        CP16(dstHi + off, hi + g);
        CP16(dstLo + off, lo + g);
    }
}

// ---------------------------------------------------------------------------
// bf16-split NT GEMM via mma.sync: C[128,256] block = A[M,K] * B[N,K]^T
// 3 MMA passes (hi*hi + hi*lo + lo*hi), fp32 accum.
// 16 warps as 4x4; warp tile 32x64 (mt=2 x nt=8). BK=64, 2-stage cp.async.
// SMEM stage: Ah(16K) Al(16K) Bh(32K) Bl(32K) = 96KB; 2 stages = 192KB.
// MODE 1: A = hidden fp32 (runtime split), B = down_W presplit; GELU -> g_h1h/l
// MODE 2: A = g_h1 presplit, B = expert_W[e] presplit; +bias/pass + emb -> g_h2h/l
// MODE 3: A = g_h2 presplit, B = up_W presplit; +bias+residual -> g_pre fp32
// ---------------------------------------------------------------------------
#define A_OFF 0u
#define AL_OFF 16384u
#define BH_OFF 32768u
#define BL_OFF 65536u
#define STAGE_B 98304u
#define SMEM_BYTES (2u * STAGE_B)

template <int MODE>
__global__ __launch_bounds__(512, 1)
void hmma_gemm(const float* __restrict__ Afp,
               const float* __restrict__ bias,
               const float* __restrict__ extra) {
    constexpr int K  = (MODE == 1) ? Dv : Av;
    constexpr int N  = (MODE == 3) ? Dv : Av;
    constexpr int NC = K / 64;

    extern __shared__ char sm[];
    const uint32_t sbase = smem_u32(sm);

    const int tid  = threadIdx.x;
    const int lane = tid & 31;
    const int wid  = tid >> 5;
    const int wm   = wid & 3;     // warp row: 4 x 32 = 128 M
    const int wn   = wid >> 2;    // warp col: 4 x 64 = 256 N

    int m0;
    const int n0 = blockIdx.x * 256;
    const __nv_bfloat16 *Ah = nullptr, *Al = nullptr, *Bh, *Bl;
    const float* biasp = bias;
    const float* embp = nullptr;
    int valid = 1;
    if (MODE == 1) {
        m0 = blockIdx.y * 128;
        Bh = g_dwh; Bl = g_dwl;
    } else if (MODE == 2) {
        const int b = blockIdx.z;
        const int e = g_idx[b];
        valid = g_valid[b];
        m0 = b * Sv + blockIdx.y * 128;
        Ah = g_h1h; Al = g_h1l;
        Bh = g_ewh + (size_t)e * Av * Av;
        Bl = g_ewl + (size_t)e * Av * Av;
        biasp = bias + (size_t)e * Av;
        embp = extra + (size_t)e * Av;
    } else {
        m0 = blockIdx.y * 128;
        Ah = g_h2h; Al = g_h2l;
        Bh = g_uwh; Bl = g_uwl;
    }

    const float* ArowF = (MODE == 1) ? (Afp + (size_t)m0 * K) : nullptr;
    const __nv_bfloat16* ArowH = (MODE != 1) ? (Ah + (size_t)m0 * K) : nullptr;
    const __nv_bfloat16* ArowL = (MODE != 1) ? (Al + (size_t)m0 * K) : nullptr;
    const __nv_bfloat16* BrowH = Bh + (size_t)n0 * K;
    const __nv_bfloat16* BrowL = Bl + (size_t)n0 * K;

    // MODE1 A register-split coords (128x64 fp32 -> 2048 float4, 4/thread)
    int lr[4], lc[4];
    uint32_t soff[4];
    float4 pA[4];
    if (MODE == 1) {
#pragma unroll
        for (int i = 0; i < 4; i++) {
            const int idx = tid + i * 512;
            lr[i] = idx >> 4;
            lc[i] = (idx & 15) * 4;
            soff[i] = (uint32_t)(lr[i] * 128) +
                      (uint32_t)((lc[i] * 2) ^ ((lr[i] & 7) << 4));
            pA[i] = *(const float4*)(ArowF + (size_t)lr[i] * K + lc[i]);
        }
    }

    // Prologue: issue chunk 0 copies
    {
        const uint32_t sb = sbase;
        if (MODE != 1)
            load_presplit<128>(sb + A_OFF, sb + AL_OFF, ArowH, ArowL, tid, K, 0);
        load_presplit<256>(sb + BH_OFF, sb + BL_OFF, BrowH, BrowL, tid, K, 0);
        CPCOMMIT();
    }

    float acc[2][8][4];
#pragma unroll
    for (int mt = 0; mt < 2; mt++)
#pragma unroll
        for (int nt = 0; nt < 8; nt++)
#pragma unroll
            for (int q = 0; q < 4; q++) acc[mt][nt][q] = 0.f;

    for (int c = 0; c < NC; c++) {
        const int s = c & 1;
        const uint32_t sb = sbase + s * STAGE_B;

        if (MODE == 1) {
            char* smc = sm + s * STAGE_B;
#pragma unroll
            for (int i = 0; i < 4; i++)
                split_store(smc + A_OFF, smc + AL_OFF, soff[i], pA[i]);
        }
        CPWAIT0();
        __syncthreads();

        if (c + 1 < NC) {
            const uint32_t nb = sbase + (s ^ 1) * STAGE_B;
            const int k0 = (c + 1) * 64;
            if (MODE != 1)
                load_presplit<128>(nb + A_OFF, nb + AL_OFF, ArowH, ArowL, tid, K, k0);
            load_presplit<256>(nb + BH_OFF, nb + BL_OFF, BrowH, BrowL, tid, K, k0);
            CPCOMMIT();
            if (MODE == 1) {
#pragma unroll
                for (int i = 0; i < 4; i++)
                    pA[i] = *(const float4*)(ArowF + (size_t)lr[i] * K + k0 + lc[i]);
            }
        }

        // compute chunk: 4 k16 steps x 3 split passes, warp tile 32x64
#pragma unroll
        for (int k16 = 0; k16 < 4; k16++) {
            uint32_t ah[2][4], al[2][4], bh[4][4], bl[4][4];
#pragma unroll
            for (int mt = 0; mt < 2; mt++) {
                const int row = wm * 32 + mt * 16 + (lane & 15);
                const int kc  = k16 * 16 + (lane >> 4) * 8;
                const uint32_t off = (uint32_t)(row * 128) +
                                     (uint32_t)((kc * 2) ^ ((row & 7) << 4));
                LDSM4(ah[mt], sb + A_OFF + off);
                LDSM4(al[mt], sb + AL_OFF + off);
            }
#pragma unroll
            for (int p = 0; p < 4; p++) {
                const int g    = lane >> 3;
                const int nrow = wn * 64 + p * 16 + (g >> 1) * 8 + (lane & 7);
                const int kc   = k16 * 16 + (g & 1) * 8;
                const uint32_t off = (uint32_t)(nrow * 128) +
                                     (uint32_t)((kc * 2) ^ ((nrow & 7) << 4));
                LDSM4(bh[p], sb + BH_OFF + off);
                LDSM4(bl[p], sb + BL_OFF + off);
            }
#pragma unroll
            for (int mt = 0; mt < 2; mt++)
#pragma unroll
                for (int nt = 0; nt < 8; nt++) {
                    const int p = nt >> 1;
                    const int q = (nt & 1) * 2;
                    MMA_OP(acc[mt][nt], ah[mt], bh[p][q], bh[p][q + 1]);  // hi*hi
                    MMA_OP(acc[mt][nt], ah[mt], bl[p][q], bl[p][q + 1]);  // hi*lo
                    MMA_OP(acc[mt][nt], al[mt], bh[p][q], bh[p][q + 1]);  // lo*hi
                }
        }
        __syncthreads();
    }

    // ---- epilogue ----
#pragma unroll
    for (int mt = 0; mt < 2; mt++)
#pragma unroll
        for (int half = 0; half < 2; half++) {
            const int r = m0 + wm * 32 + mt * 16 + (lane >> 2) + half * 8;
#pragma unroll
            for (int nt = 0; nt < 8; nt++) {
                const int col = n0 + wn * 64 + nt * 8 + (lane & 3) * 2;
                float vx = acc[mt][nt][half * 2];
                float vy = acc[mt][nt][half * 2 + 1];
                if (MODE == 1) {
                    const float2 bi = *(const float2*)(bias + col);
                    vx = gelu_exact(vx + bi.x);
                    vy = gelu_exact(vy + bi.y);
                    ep_split(g_h1h, g_h1l, (size_t)r * Av + col, vx, vy);
                } else if (MODE == 2) {
                    if (valid) {
                        const float2 bi = *(const float2*)(biasp + col);
                        vx += bi.x; vy += bi.y;
                    } else {
                        const size_t o = (size_t)r * Av + col;
                        uint32_t ph = *(const uint32_t*)(g_h1h + o);
                        uint32_t pl = *(const uint32_t*)(g_h1l + o);
                        float2 fh = __bfloat1622float2(*(__nv_bfloat162*)&ph);
                        float2 fl = __bfloat1622float2(*(__nv_bfloat162*)&pl);
                        vx = fh.x + fl.x;
                        vy = fh.y + fl.y;
                    }
                    const float2 em = *(const float2*)(embp + col);
                    vx += em.x; vy += em.y;
                    ep_split(g_h2h, g_h2l, (size_t)r * Av + col, vx, vy);
                } else {
                    const float2 bi = *(const float2*)(bias + col);
                    const float2 rs = *(const float2*)(extra + (size_t)r * Dv + col);
                    vx += bi.x + rs.x;
                    vy += bi.y + rs.y;
                    *(float2*)(g_pre + (size_t)r * N + col) = make_float2(vx, vy);
                }
            }
        }
}

// ---------------------------------------------------------------------------
// LayerNorm over D=1024 (one 256-thread block per row, 4 elems/thread)
// ---------------------------------------------------------------------------
__global__ __launch_bounds__(256)
void ln_kernel(const float* __restrict__ gamma,
               const float* __restrict__ beta,
               float* __restrict__ out) {
    const int row = blockIdx.x;
    const int t = threadIdx.x;
    const float4 v = *(const float4*)(g_pre + (size_t)row * Dv + t * 4);

    __shared__ float red1[8];
    __shared__ float red2[8];

    float s = v.x + v.y + v.z + v.w;
#pragma unroll
    for (int o = 16; o; o >>= 1) s += __shfl_xor_sync(0xFFFFFFFFu, s, o);
    if ((t & 31) == 0) red1[t >> 5] = s;
    __syncthreads();
    float tot = 0.f;
#pragma unroll
    for (int i = 0; i < 8; i++) tot += red1[i];
    const float mu = tot * (1.0f / Dv);

    const float dx = v.x - mu, dy = v.y - mu, dz = v.z - mu, dw = v.w - mu;
    float s2 = dx * dx + dy * dy + dz * dz + dw * dw;
#pragma unroll
    for (int o = 16; o; o >>= 1) s2 += __shfl_xor_sync(0xFFFFFFFFu, s2, o);
    if ((t & 31) == 0) red2[t >> 5] = s2;
    __syncthreads();
    float tot2 = 0.f;
#pragma unroll
    for (int i = 0; i < 8; i++) tot2 += red2[i];
    const float inv = rsqrtf(tot2 * (1.0f / Dv) + 1e-5f);

    const int c = t * 4;
    const float4 gm = *(const float4*)(gamma + c);
    const float4 bt = *(const float4*)(beta + c);
    float4 o;
    o.x = dx * inv * gm.x + bt.x;
    o.y = dy * inv * gm.y + bt.y;
    o.z = dz * inv * gm.z + bt.z;
    o.w = dw * inv * gm.w + bt.w;
    *(float4*)(out + (size_t)row * Dv + c) = o;
}

// ---------------------------------------------------------------------------
extern "C" void kernel_launch(void* const* d_in, const int* in_sizes, int n_in,
                              void* d_out, int out_size) {
    const float* hidden     = (const float*)d_in[0];
    const int*   dom        = (const int*)d_in[1];
    const float* down_W     = (const float*)d_in[2];
    const float* down_b     = (const float*)d_in[3];
    const float* up_W       = (const float*)d_in[4];
    const float* up_b       = (const float*)d_in[5];
    const float* expert_W   = (const float*)d_in[6];
    const float* expert_b   = (const float*)d_in[7];
    const float* domain_emb = (const float*)d_in[8];
    const float* gamma      = (const float*)d_in[9];
    const float* beta       = (const float*)d_in[10];
    float* out = (float*)d_out;

    cudaFuncSetAttribute(hmma_gemm<1>, cudaFuncAttributeMaxDynamicSharedMemorySize, SMEM_BYTES);
    cudaFuncSetAttribute(hmma_gemm<2>, cudaFuncAttributeMaxDynamicSharedMemorySize, SMEM_BYTES);
    cudaFuncSetAttribute(hmma_gemm<3>, cudaFuncAttributeMaxDynamicSharedMemorySize, SMEM_BYTES);

    prep_ids<<<1, 1>>>(dom);

    // one-time weight splits (device globals)
    __nv_bfloat16 *dwh, *dwl, *uwh, *uwl, *ewh, *ewl;
    cudaGetSymbolAddress((void**)&dwh, g_dwh);
    cudaGetSymbolAddress((void**)&dwl, g_dwl);
    cudaGetSymbolAddress((void**)&uwh, g_uwh);
    cudaGetSymbolAddress((void**)&uwl, g_uwl);
    cudaGetSymbolAddress((void**)&ewh, g_ewh);
    cudaGetSymbolAddress((void**)&ewl, g_ewl);
    split_w<<<256, 512>>>(down_W, dwh, dwl, Av * Dv);
    split_w<<<256, 512>>>(up_W, uwh, uwl, Dv * Av);
    split_w<<<512, 512>>>(expert_W, ewh, ewl, Ev * Av * Av);

    // Stage 1: down-proj + GELU   (M=32768, N=256,  K=1024)
    hmma_gemm<1><<<dim3(1, Mrows / 128), 512, SMEM_BYTES>>>(hidden, down_b, nullptr);
    // Stage 2: per-batch expert   (per batch M=1024, N=256, K=256)
    hmma_gemm<2><<<dim3(1, Sv / 128, Bv), 512, SMEM_BYTES>>>(nullptr, expert_b, domain_emb);
    // Stage 3: up-proj + residual (M=32768, N=1024, K=256)
    hmma_gemm<3><<<dim3(Dv / 256, Mrows / 128), 512, SMEM_BYTES>>>(nullptr, up_b, hidden);
    // Stage 4: LayerNorm
    ln_kernel<<<Mrows, 256>>>(gamma, beta, out);
}